// round 4
// baseline (speedup 1.0000x reference)
#include <cuda_runtime.h>

#define FULL 0xffffffffu
typedef unsigned long long u64;

__device__ __forceinline__ u64 pk2(float x, float y) {
    u64 r; asm("mov.b64 %0,{%1,%2};" : "=l"(r) : "f"(x), "f"(y)); return r;
}
__device__ __forceinline__ void upk2(u64 v, float& x, float& y) {
    asm("mov.b64 {%0,%1},%2;" : "=f"(x), "=f"(y) : "l"(v));
}
__device__ __forceinline__ u64 fma2_(u64 a, u64 b, u64 c) {
    u64 d; asm("fma.rn.f32x2 %0,%1,%2,%3;" : "=l"(d) : "l"(a), "l"(b), "l"(c)); return d;
}
__device__ __forceinline__ u64 mul2_(u64 a, u64 b) {
    u64 d; asm("mul.rn.f32x2 %0,%1,%2;" : "=l"(d) : "l"(a), "l"(b)); return d;
}
__device__ __forceinline__ float2 cmulf(float2 a, float2 b) {
    return make_float2(a.x * b.x - a.y * b.y, a.x * b.y + a.y * b.x);
}

// Layout: each half-warp (16 lanes) holds one batch element.
// State index s (8 bits): bits {7,5,3,1} -> k register index bits {3,2,1,0};
//                         bits {6,4,2,0} -> half-lane (hl) bits {3,2,1,0}.
// v[k] holds packed (re,im).

// Local gate: control in lane bit LB, target in k bit KB.
template <int LB, int KB, bool ISRX>
__device__ __forceinline__ void gate_local(u64 (&v)[16], float c, float s, int hl) {
    const bool ctrl = ((hl >> LB) & 1) != 0;
    const float cE = ctrl ? c : 1.0f;
    const float sE = ctrl ? s : 0.0f;
    const u64 cc = pk2(cE, cE);
#pragma unroll
    for (int k = 0; k < 16; ++k) {
        if (k & (1 << KB)) continue;
        const int k1 = k | (1 << KB);
        if (ISRX) {
            const u64 sn = pk2(sE, -sE);
            float r0, i0, r1, i1;
            upk2(v[k], r0, i0);
            upk2(v[k1], r1, i1);
            v[k]  = fma2_(cc, v[k],  mul2_(sn, pk2(i1, r1)));
            v[k1] = fma2_(cc, v[k1], mul2_(sn, pk2(i0, r0)));
        } else {
            const u64 old0 = v[k];
            v[k]  = fma2_(cc, v[k],  mul2_(pk2(-sE, -sE), v[k1]));
            v[k1] = fma2_(cc, v[k1], mul2_(pk2(sE, sE), old0));
        }
    }
}

// Shuffle gate: control in k bit KB (compile-time skip of ctrl=0 regs),
// target in lane bit LB. 64-bit shuffle delivers the partner pre-packed.
template <int KB, int LB, bool ISRX>
__device__ __forceinline__ void gate_shfl(u64 (&v)[16], float c, float s, int hl) {
    const u64 cc = pk2(c, c);
    u64 smul;
    if (ISRX) {
        smul = pk2(s, -s);
    } else {
        const float sg = ((hl >> LB) & 1) ? s : -s;
        smul = pk2(sg, sg);
    }
#pragma unroll
    for (int k = 0; k < 16; ++k) {
        if (!(k & (1 << KB))) continue;   // control bit = 0: identity
        u64 p = __shfl_xor_sync(FULL, v[k], 1 << LB);
        if (ISRX) {                       // need (pi, pr)
            float pr, pi; upk2(p, pr, pi);
            p = pk2(pi, pr);
        }
        v[k] = fma2_(cc, v[k], mul2_(smul, p));
    }
}

__global__ __launch_bounds__(128)
void quanv_kernel(const float* __restrict__ X, const float* __restrict__ W,
                  float* __restrict__ out, int bs) {
    const int warp0 = (blockIdx.x * blockDim.x + threadIdx.x) >> 5;
    const int lane = threadIdx.x & 31;
    const int e = lane >> 4;          // element within warp
    const int hl = lane & 15;         // half-lane
    const int half = lane & 16;       // half-warp base for shuffles
    const int q = lane & 7;
    const int totalWarps = gridDim.x * (blockDim.x >> 5);

    // ===== Loop-invariant: entangler weight sincos (lanes 0..15 hold 16 angles)
    const float wangle = (lane < 16) ? W[(lane >> 3) * 16 + (lane & 7)] : 0.f;
    float cw, sw;
    __sincosf(0.5f * wangle, &sw, &cw);
    const float Rv = 0.70710678118654752440f;

    for (long w = warp0; w * 2 < bs; w += totalWarps) {
        const long elem = w * 2 + e;
        const bool valid = elem < bs;
        const float* __restrict__ x = X + (valid ? elem : 0) * 64;

        // ===== Phase 1: per-wire 2-vectors. wire q = lane&7 (lanes 8..15 duplicate).
        float2 A = make_float2(Rv, 0.f), B = make_float2(Rv, 0.f);
#pragma unroll
        for (int i = 0; i < 9; ++i) {
            const int idx = q * 9 + i;
            const bool ok = (idx < 64);
            const float th = x[ok ? idx : 0];
            float c, s;
            __sincosf(0.5f * th, &s, &c);
            if (ok) {
                if ((i & 1) == 0) {
                    A = cmulf(A, make_float2(c, -s));
                    B = cmulf(B, make_float2(c, s));
                } else {
                    float2 A2 = make_float2(c * A.x - s * B.x, c * A.y - s * B.y);
                    float2 B2 = make_float2(s * A.x + c * B.x, s * A.y + c * B.y);
                    A = A2; B = B2;
                }
            }
        }
        // lane half+w presents A_w, lane half+8+w presents B_w.
        float2 V = (lane & 8) ? B : A;

        // lp: product over lane-held wires 1,3,5,7 (hl bits 3,2,1,0 select component).
        float2 lp;
        {
            const int b = (hl >> 3) & 1;
            lp.x = __shfl_sync(FULL, V.x, half | (b << 3) | 1);
            lp.y = __shfl_sync(FULL, V.y, half | (b << 3) | 1);
        }
        {
            const int b = (hl >> 2) & 1;
            float2 t;
            t.x = __shfl_sync(FULL, V.x, half | (b << 3) | 3);
            t.y = __shfl_sync(FULL, V.y, half | (b << 3) | 3);
            lp = cmulf(lp, t);
        }
        {
            const int b = (hl >> 1) & 1;
            float2 t;
            t.x = __shfl_sync(FULL, V.x, half | (b << 3) | 5);
            t.y = __shfl_sync(FULL, V.y, half | (b << 3) | 5);
            lp = cmulf(lp, t);
        }
        {
            const int b = hl & 1;
            float2 t;
            t.x = __shfl_sync(FULL, V.x, half | (b << 3) | 7);
            t.y = __shfl_sync(FULL, V.y, half | (b << 3) | 7);
            lp = cmulf(lp, t);
        }

        // k-held wires 0,2,4,6: both components.
        float2 w0[2], w2[2], w4[2], w6[2];
#pragma unroll
        for (int b = 0; b < 2; ++b) {
            w0[b].x = __shfl_sync(FULL, V.x, half | (b << 3) | 0);
            w0[b].y = __shfl_sync(FULL, V.y, half | (b << 3) | 0);
            w2[b].x = __shfl_sync(FULL, V.x, half | (b << 3) | 2);
            w2[b].y = __shfl_sync(FULL, V.y, half | (b << 3) | 2);
            w4[b].x = __shfl_sync(FULL, V.x, half | (b << 3) | 4);
            w4[b].y = __shfl_sync(FULL, V.y, half | (b << 3) | 4);
            w6[b].x = __shfl_sync(FULL, V.x, half | (b << 3) | 6);
            w6[b].y = __shfl_sync(FULL, V.y, half | (b << 3) | 6);
        }

        // Build product state: k = (w0bit<<3)|(w2bit<<2)|(w4bit<<1)|w6bit.
        u64 v[16];
        {
            float2 d8[8];
#pragma unroll
            for (int i = 0; i < 2; ++i)
#pragma unroll
                for (int j = 0; j < 2; ++j) {
                    const float2 c02 = cmulf(cmulf(w0[i], w2[j]), lp);
#pragma unroll
                    for (int n = 0; n < 2; ++n)
                        d8[(((i << 1) | j) << 1) | n] = cmulf(c02, w4[n]);
                }
#pragma unroll
            for (int k = 0; k < 16; ++k) {
                const float2 t = cmulf(d8[k >> 1], w6[k & 1]);
                v[k] = pk2(t.x, t.y);
            }
        }

        // ===== Phase 2: entangling layers.
#define CGS(L, CI, KB, LB, RX)                                       \
        {                                                            \
            const float c_ = __shfl_sync(FULL, cw, (L) * 8 + (CI));  \
            const float s_ = __shfl_sync(FULL, sw, (L) * 8 + (CI));  \
            gate_shfl<KB, LB, RX>(v, c_, s_, hl);                    \
        }
#define CGL(L, CI, LB, KB, RX)                                       \
        {                                                            \
            const float c_ = __shfl_sync(FULL, cw, (L) * 8 + (CI));  \
            const float s_ = __shfl_sync(FULL, sw, (L) * 8 + (CI));  \
            gate_local<LB, KB, RX>(v, c_, s_, hl);                   \
        }
        // layer 0 (RX)
        CGS(0, 0, 3, 3, true)   // (7,6)
        CGL(0, 1, 3, 2, true)   // (6,5)
        CGS(0, 2, 2, 2, true)   // (5,4)
        CGL(0, 3, 2, 1, true)   // (4,3)
        CGS(0, 4, 1, 1, true)   // (3,2)
        CGL(0, 5, 1, 0, true)   // (2,1)
        CGS(0, 6, 0, 0, true)   // (1,0)
        CGL(0, 7, 0, 3, true)   // (0,7)
        // layer 1 (RY)
        CGS(1, 0, 3, 3, false)
        CGL(1, 1, 3, 2, false)
        CGS(1, 2, 2, 2, false)
        CGL(1, 3, 2, 1, false)
        CGS(1, 4, 1, 1, false)
        CGL(1, 5, 1, 0, false)
        CGS(1, 6, 0, 0, false)
        CGL(1, 7, 0, 3, false)
#undef CGS
#undef CGL

        // ===== Measurement
        float p[16];
#pragma unroll
        for (int k = 0; k < 16; ++k) {
            float x2, y2;
            upk2(mul2_(v[k], v[k]), x2, y2);
            p[k] = x2 + y2;
        }
        float s1[8], ow6 = 0.f;
#pragma unroll
        for (int j = 0; j < 8; ++j) {
            s1[j] = p[2 * j] + p[2 * j + 1];
            ow6 += p[2 * j] - p[2 * j + 1];
        }
        float s2[4], ow4 = 0.f;
#pragma unroll
        for (int j = 0; j < 4; ++j) {
            s2[j] = s1[2 * j] + s1[2 * j + 1];
            ow4 += s1[2 * j] - s1[2 * j + 1];
        }
        const float s30 = s2[0] + s2[1], s31 = s2[2] + s2[3];
        float ow2 = (s2[0] - s2[1]) + (s2[2] - s2[3]);
        float ow0 = s30 - s31;
        float sumP = s30 + s31;

#pragma unroll
        for (int m = 8; m; m >>= 1) {
            ow0 += __shfl_xor_sync(FULL, ow0, m);
            ow2 += __shfl_xor_sync(FULL, ow2, m);
            ow4 += __shfl_xor_sync(FULL, ow4, m);
            ow6 += __shfl_xor_sync(FULL, ow6, m);
        }
        float wv = sumP;
#pragma unroll
        for (int st = 0; st < 4; ++st) {
            const int m = 1 << st;
            const float pg = __shfl_xor_sync(FULL, wv, m);
            const float sg = (hl & m) ? -1.f : 1.f;
            wv = fmaf(wv, sg, pg);
        }
        const float ow1 = __shfl_sync(FULL, wv, half | 8);
        const float ow3 = __shfl_sync(FULL, wv, half | 4);
        const float ow5 = __shfl_sync(FULL, wv, half | 2);
        const float ow7 = __shfl_sync(FULL, wv, half | 1);

        if (hl == 0 && valid) {
            float4* po = (float4*)(out + elem * 8);
            po[0] = make_float4(ow0, ow1, ow2, ow3);
            po[1] = make_float4(ow4, ow5, ow6, ow7);
        }
    }
}

extern "C" void kernel_launch(void* const* d_in, const int* in_sizes, int n_in,
                              void* d_out, int out_size) {
    const float* X = (const float*)d_in[0];
    const float* W = (const float*)d_in[1];
    float* out = (float*)d_out;
    const int bs = in_sizes[0] / 64;
    const int pairs = (bs + 1) / 2;          // element-pairs (one per warp-iter)
    const int ITERS = 2;                     // pairs per warp
    const int warps = (pairs + ITERS - 1) / ITERS;
    const int threads = 128;
    const int wpb = threads / 32;
    const int blocks = (warps + wpb - 1) / wpb;
    quanv_kernel<<<blocks, threads>>>(X, W, out, bs);
}